// round 1
// baseline (speedup 1.0000x reference)
#include <cuda_runtime.h>
#include <math.h>

#define BSZ 2
#define SEQ 2048
#define DIM 1024
#define NH  16
#define HD  64

// Scratch: qkv projection output and attention output (no cudaMalloc allowed).
__device__ float g_qkv[(size_t)BSZ * SEQ * 3 * DIM];   // [B,S,3D], per-head interleave h*192 + {q:0..63,k:64..127,v:128..191}
__device__ float g_attn[(size_t)BSZ * SEQ * DIM];      // [B,S,D] head-major columns h*64+d

// ---------------------------------------------------------------------------
// SGEMM: C[M,N] = A[M,K] @ B[K,N] + bias[N], optionally * (gamma[N]+1)
// 128x128 tile, BK=8, 256 threads, 8x8 per thread (2x2 blocks of 4x4).
// ---------------------------------------------------------------------------
template<int EPI>
__global__ __launch_bounds__(256) void sgemm_kernel(
    const float* __restrict__ A, const float* __restrict__ B,
    const float* __restrict__ bias, const float* __restrict__ gamma,
    float* __restrict__ C, int M, int N, int K)
{
    __shared__ float As[8][132];   // transposed A tile, padded
    __shared__ float Bs[8][128];

    int t  = threadIdx.x;
    int tx = t & 15, ty = t >> 4;

    const float* Ab = A + (size_t)blockIdx.y * 128 * K;
    const float* Bb = B + (size_t)blockIdx.x * 128;

    int a_row = t >> 1, a_col = (t & 1) * 4;   // A tile 128x8 as float4
    int b_row = t >> 5, b_col = (t & 31) * 4;  // B tile 8x128 as float4

    float acc[8][8];
    #pragma unroll
    for (int i = 0; i < 8; i++)
        #pragma unroll
        for (int j = 0; j < 8; j++) acc[i][j] = 0.f;

    for (int k0 = 0; k0 < K; k0 += 8) {
        float4 av = *(const float4*)(Ab + (size_t)a_row * K + k0 + a_col);
        As[a_col + 0][a_row] = av.x;
        As[a_col + 1][a_row] = av.y;
        As[a_col + 2][a_row] = av.z;
        As[a_col + 3][a_row] = av.w;
        *(float4*)(&Bs[b_row][b_col]) =
            *(const float4*)(Bb + (size_t)(k0 + b_row) * N + b_col);
        __syncthreads();

        #pragma unroll
        for (int kk = 0; kk < 8; kk++) {
            float ar[8], br[8];
            *(float4*)(ar)     = *(float4*)(&As[kk][ty * 4]);
            *(float4*)(ar + 4) = *(float4*)(&As[kk][64 + ty * 4]);
            *(float4*)(br)     = *(float4*)(&Bs[kk][tx * 4]);
            *(float4*)(br + 4) = *(float4*)(&Bs[kk][64 + tx * 4]);
            #pragma unroll
            for (int i = 0; i < 8; i++)
                #pragma unroll
                for (int j = 0; j < 8; j++)
                    acc[i][j] += ar[i] * br[j];
        }
        __syncthreads();
    }

    #pragma unroll
    for (int ii = 0; ii < 2; ii++) {
        #pragma unroll
        for (int i = 0; i < 4; i++) {
            int row = blockIdx.y * 128 + ii * 64 + ty * 4 + i;
            #pragma unroll
            for (int jj = 0; jj < 2; jj++) {
                int col = blockIdx.x * 128 + jj * 64 + tx * 4;
                float4 r;
                r.x = acc[ii * 4 + i][jj * 4 + 0] + bias[col + 0];
                r.y = acc[ii * 4 + i][jj * 4 + 1] + bias[col + 1];
                r.z = acc[ii * 4 + i][jj * 4 + 2] + bias[col + 2];
                r.w = acc[ii * 4 + i][jj * 4 + 3] + bias[col + 3];
                if (EPI == 1) {
                    r.x *= gamma[col + 0] + 1.f;
                    r.y *= gamma[col + 1] + 1.f;
                    r.z *= gamma[col + 2] + 1.f;
                    r.w *= gamma[col + 3] + 1.f;
                }
                *(float4*)(C + (size_t)row * N + col) = r;
            }
        }
    }
}

// ---------------------------------------------------------------------------
// Flash-style attention, fp32. One block = 64 queries of one (b,h).
// 256 threads; thread owns 4 query rows x 4 cols (scores) / 4 dims (output).
// Online softmax with key-mask bias.
// ---------------------------------------------------------------------------
__global__ __launch_bounds__(256) void attn_kernel(
    const float* __restrict__ qkv, const int* __restrict__ mask,
    float* __restrict__ out)
{
    extern __shared__ float sm[];
    float* Qs = sm;              // 64 x 68 (padded)
    float* Ks = Qs + 64 * 68;
    float* Vs = Ks + 64 * 68;
    float* Ps = Vs + 64 * 68;
    float* Mb = Ps + 64 * 68;    // 64 mask biases

    int t  = threadIdx.x;
    int b  = blockIdx.y >> 4;
    int h  = blockIdx.y & 15;
    int q0 = blockIdx.x * 64;
    int qr = (t >> 4) * 4;       // query-row base (group of 16 lanes shares rows)
    int dc = (t & 15) * 4;       // col/dim base

    const float* base = qkv + ((size_t)b * SEQ) * (3 * DIM) + h * (3 * HD);

    // Load Q tile (vectorized, coalesced)
    #pragma unroll
    for (int i = 0; i < 4; i++) {
        int idx = t + i * 256;
        int r = idx >> 4, c = (idx & 15) * 4;
        *(float4*)(&Qs[r * 68 + c]) =
            *(const float4*)(base + (size_t)(q0 + r) * (3 * DIM) + c);
    }

    float m[4], l[4], o[4][4];
    #pragma unroll
    for (int i = 0; i < 4; i++) {
        m[i] = -INFINITY; l[i] = 0.f;
        #pragma unroll
        for (int j = 0; j < 4; j++) o[i][j] = 0.f;
    }

    for (int k0 = 0; k0 < SEQ; k0 += 64) {
        __syncthreads();  // previous PV done (and first-iter Q visible)
        #pragma unroll
        for (int i = 0; i < 4; i++) {
            int idx = t + i * 256;
            int r = idx >> 4, c = (idx & 15) * 4;
            const float* rowp = base + (size_t)(k0 + r) * (3 * DIM);
            *(float4*)(&Ks[r * 68 + c]) = *(const float4*)(rowp + HD + c);
            *(float4*)(&Vs[r * 68 + c]) = *(const float4*)(rowp + 2 * HD + c);
        }
        if (t < 64) Mb[t] = mask[b * SEQ + k0 + t] ? 0.f : -1e30f;
        __syncthreads();

        // S = Q K^T (4x4 per thread)
        float s[4][4];
        #pragma unroll
        for (int i = 0; i < 4; i++)
            #pragma unroll
            for (int j = 0; j < 4; j++) s[i][j] = 0.f;

        #pragma unroll
        for (int d0 = 0; d0 < 64; d0 += 4) {
            float4 q4[4], k4[4];
            #pragma unroll
            for (int i = 0; i < 4; i++) q4[i] = *(float4*)(&Qs[(qr + i) * 68 + d0]);
            #pragma unroll
            for (int j = 0; j < 4; j++) k4[j] = *(float4*)(&Ks[(dc + j) * 68 + d0]);
            #pragma unroll
            for (int i = 0; i < 4; i++)
                #pragma unroll
                for (int j = 0; j < 4; j++)
                    s[i][j] += q4[i].x * k4[j].x + q4[i].y * k4[j].y
                             + q4[i].z * k4[j].z + q4[i].w * k4[j].w;
        }

        #pragma unroll
        for (int i = 0; i < 4; i++)
            #pragma unroll
            for (int j = 0; j < 4; j++)
                s[i][j] = s[i][j] * 0.125f + Mb[dc + j];

        // Online softmax (row group = 16 consecutive lanes)
        #pragma unroll
        for (int i = 0; i < 4; i++) {
            float rm = fmaxf(fmaxf(s[i][0], s[i][1]), fmaxf(s[i][2], s[i][3]));
            #pragma unroll
            for (int off = 1; off < 16; off <<= 1)
                rm = fmaxf(rm, __shfl_xor_sync(0xffffffffu, rm, off));
            float mn = fmaxf(m[i], rm);
            float sc = __expf(m[i] - mn);
            m[i] = mn;
            float ps = 0.f;
            #pragma unroll
            for (int j = 0; j < 4; j++) {
                float p = __expf(s[i][j] - mn);
                if (s[i][j] < -1e29f) p = 0.f;   // fully-masked guard
                s[i][j] = p;
                ps += p;
            }
            l[i] = l[i] * sc + ps;
            #pragma unroll
            for (int j = 0; j < 4; j++) o[i][j] *= sc;
            *(float4*)(&Ps[(qr + i) * 68 + dc]) =
                make_float4(s[i][0], s[i][1], s[i][2], s[i][3]);
        }
        __syncthreads();

        // O += P @ V
        #pragma unroll 8
        for (int k = 0; k < 64; k++) {
            float4 v = *(float4*)(&Vs[k * 68 + dc]);
            #pragma unroll
            for (int i = 0; i < 4; i++) {
                float p = Ps[(qr + i) * 68 + k];
                o[i][0] += p * v.x; o[i][1] += p * v.y;
                o[i][2] += p * v.z; o[i][3] += p * v.w;
            }
        }
    }

    #pragma unroll
    for (int i = 0; i < 4; i++) {
        #pragma unroll
        for (int off = 1; off < 16; off <<= 1)
            l[i] += __shfl_xor_sync(0xffffffffu, l[i], off);
        float inv = 1.f / l[i];
        float4 r = make_float4(o[i][0] * inv, o[i][1] * inv,
                               o[i][2] * inv, o[i][3] * inv);
        *(float4*)(out + (size_t)(b * SEQ + q0 + qr + i) * DIM + h * HD + dc) = r;
    }
}

// ---------------------------------------------------------------------------
extern "C" void kernel_launch(void* const* d_in, const int* in_sizes, int n_in,
                              void* d_out, int out_size)
{
    const float* x     = (const float*)d_in[0];
    const float* gamma = (const float*)d_in[1];
    const int*   mask  = (const int*)  d_in[2];
    const float* wqkv  = (const float*)d_in[3];
    const float* bqkv  = (const float*)d_in[4];
    const float* wo    = (const float*)d_in[5];
    const float* bo    = (const float*)d_in[6];
    float* out = (float*)d_out;

    float *qkv, *attn;
    cudaGetSymbolAddress((void**)&qkv,  g_qkv);
    cudaGetSymbolAddress((void**)&attn, g_attn);

    const int M = BSZ * SEQ;   // 4096

    // 1) QKV projection: [4096,1024] @ [1024,3072] + b
    sgemm_kernel<0><<<dim3(3 * DIM / 128, M / 128), 256>>>(
        x, wqkv, bqkv, nullptr, qkv, M, 3 * DIM, DIM);

    // 2) Masked multi-head attention
    size_t smem = (size_t)(4 * 64 * 68 + 64) * sizeof(float);  // ~70 KB
    cudaFuncSetAttribute(attn_kernel,
                         cudaFuncAttributeMaxDynamicSharedMemorySize, (int)smem);
    attn_kernel<<<dim3(SEQ / 64, BSZ * NH), 256, smem>>>(qkv, mask, attn);

    // 3) Output projection + bias + (gamma+1) scale
    sgemm_kernel<1><<<dim3(DIM / 128, M / 128), 256>>>(
        attn, wo, bo, gamma, out, M, DIM, DIM);
}

// round 3
// speedup vs baseline: 1.9840x; 1.9840x over previous
#include <cuda_runtime.h>
#include <math.h>
#include <stdint.h>

#define BSZ 2
#define SEQ 2048
#define DIM 1024
#define NH  16
#define HD  64
#define SCALE 0.125f

// Scratch (no cudaMalloc allowed)
__device__ float g_qkv[(size_t)BSZ * SEQ * 3 * DIM];   // [B,S,3D] head-interleaved: h*192 + {q,k,v}
__device__ float g_attn[(size_t)BSZ * SEQ * DIM];      // [B,S,D]

// ---------------------------------------------------------------------------
// tf32 helpers
// ---------------------------------------------------------------------------
__device__ __forceinline__ uint32_t f2t(float x) {
    uint32_t u; asm("cvt.rna.tf32.f32 %0, %1;" : "=r"(u) : "f"(x)); return u;
}
__device__ __forceinline__ float tf32r(float x) { return __uint_as_float(f2t(x)); }

__device__ __forceinline__ void mma8(float* c, const uint32_t* a, const uint32_t* b) {
    asm volatile(
        "mma.sync.aligned.m16n8k8.row.col.f32.tf32.tf32.f32 "
        "{%0,%1,%2,%3}, {%4,%5,%6,%7}, {%8,%9}, {%0,%1,%2,%3};\n"
        : "+f"(c[0]), "+f"(c[1]), "+f"(c[2]), "+f"(c[3])
        : "r"(a[0]), "r"(a[1]), "r"(a[2]), "r"(a[3]), "r"(b[0]), "r"(b[1]));
}

// ---------------------------------------------------------------------------
// TF32 GEMM: C[M,N] = A[M,K] @ B[K,N] + bias, optional *(gamma+1)
// A always hi/lo split. SPLITB=1 -> 3xTF32 (near-fp32 exact).
// Block 128x128, BK=16, 256 threads, 8 warps as 4(m) x 2(n), warp tile 32x64.
// ---------------------------------------------------------------------------
template<int SPLITB, int EPI>
__global__ __launch_bounds__(256) void gemm_tf32(
    const float* __restrict__ A, const float* __restrict__ B,
    const float* __restrict__ bias, const float* __restrict__ gamma,
    float* __restrict__ C, int M, int N, int K)
{
    __shared__ float Ahi[128][20], Alo[128][20];
    __shared__ float Bhi[16][136], Blo[16][136];

    int t = threadIdx.x, lane = t & 31, w = t >> 5;
    int wy = w >> 1, wx = w & 1;

    const float* Ab = A + (size_t)blockIdx.y * 128 * K;
    const float* Bb = B + (size_t)blockIdx.x * 128;

    float acc[2][8][4];
    #pragma unroll
    for (int mt = 0; mt < 2; mt++)
        #pragma unroll
        for (int nt = 0; nt < 8; nt++)
            #pragma unroll
            for (int i = 0; i < 4; i++) acc[mt][nt][i] = 0.f;

    for (int k0 = 0; k0 < K; k0 += 16) {
        #pragma unroll
        for (int i = 0; i < 2; i++) {
            int idx = t + i * 256;
            int r = idx >> 2, c = (idx & 3) * 4;
            float4 a4 = *(const float4*)(Ab + (size_t)r * K + k0 + c);
            float h;
            h = tf32r(a4.x); Ahi[r][c+0] = h; Alo[r][c+0] = tf32r(a4.x - h);
            h = tf32r(a4.y); Ahi[r][c+1] = h; Alo[r][c+1] = tf32r(a4.y - h);
            h = tf32r(a4.z); Ahi[r][c+2] = h; Alo[r][c+2] = tf32r(a4.z - h);
            h = tf32r(a4.w); Ahi[r][c+3] = h; Alo[r][c+3] = tf32r(a4.w - h);
        }
        #pragma unroll
        for (int i = 0; i < 2; i++) {
            int idx = t + i * 256;
            int r = idx >> 5, c = (idx & 31) * 4;
            float4 b4 = *(const float4*)(Bb + (size_t)(k0 + r) * N + c);
            float h;
            h = tf32r(b4.x); Bhi[r][c+0] = h; if (SPLITB) Blo[r][c+0] = tf32r(b4.x - h);
            h = tf32r(b4.y); Bhi[r][c+1] = h; if (SPLITB) Blo[r][c+1] = tf32r(b4.y - h);
            h = tf32r(b4.z); Bhi[r][c+2] = h; if (SPLITB) Blo[r][c+2] = tf32r(b4.z - h);
            h = tf32r(b4.w); Bhi[r][c+3] = h; if (SPLITB) Blo[r][c+3] = tf32r(b4.w - h);
        }
        __syncthreads();

        #pragma unroll
        for (int ks = 0; ks < 2; ks++) {
            uint32_t ah[2][4], al[2][4], bh[8][2], bl[8][2];
            #pragma unroll
            for (int mt = 0; mt < 2; mt++) {
                int r = wy * 32 + mt * 16 + (lane >> 2);
                int c = ks * 8 + (lane & 3);
                ah[mt][0] = __float_as_uint(Ahi[r][c]);
                ah[mt][1] = __float_as_uint(Ahi[r + 8][c]);
                ah[mt][2] = __float_as_uint(Ahi[r][c + 4]);
                ah[mt][3] = __float_as_uint(Ahi[r + 8][c + 4]);
                al[mt][0] = __float_as_uint(Alo[r][c]);
                al[mt][1] = __float_as_uint(Alo[r + 8][c]);
                al[mt][2] = __float_as_uint(Alo[r][c + 4]);
                al[mt][3] = __float_as_uint(Alo[r + 8][c + 4]);
            }
            #pragma unroll
            for (int nt = 0; nt < 8; nt++) {
                int n  = wx * 64 + nt * 8 + (lane >> 2);
                int kk = ks * 8 + (lane & 3);
                bh[nt][0] = __float_as_uint(Bhi[kk][n]);
                bh[nt][1] = __float_as_uint(Bhi[kk + 4][n]);
                if (SPLITB) {
                    bl[nt][0] = __float_as_uint(Blo[kk][n]);
                    bl[nt][1] = __float_as_uint(Blo[kk + 4][n]);
                }
            }
            #pragma unroll
            for (int mt = 0; mt < 2; mt++)
                #pragma unroll
                for (int nt = 0; nt < 8; nt++) {
                    mma8(acc[mt][nt], ah[mt], bh[nt]);
                    mma8(acc[mt][nt], al[mt], bh[nt]);
                    if (SPLITB) mma8(acc[mt][nt], ah[mt], bl[nt]);
                }
        }
        __syncthreads();
    }

    int r_base = blockIdx.y * 128 + wy * 32 + (lane >> 2);
    int c_base = blockIdx.x * 128 + wx * 64 + 2 * (lane & 3);
    #pragma unroll
    for (int nt = 0; nt < 8; nt++) {
        int col = c_base + nt * 8;
        float2 bi = *(const float2*)&bias[col];
        float g0 = 1.f, g1 = 1.f;
        if (EPI) {
            float2 gm = *(const float2*)&gamma[col];
            g0 = gm.x + 1.f; g1 = gm.y + 1.f;
        }
        #pragma unroll
        for (int mt = 0; mt < 2; mt++) {
            int ra = r_base + mt * 16;
            float2 v0, v1;
            v0.x = acc[mt][nt][0] + bi.x;
            v0.y = acc[mt][nt][1] + bi.y;
            v1.x = acc[mt][nt][2] + bi.x;
            v1.y = acc[mt][nt][3] + bi.y;
            if (EPI) { v0.x *= g0; v0.y *= g1; v1.x *= g0; v1.y *= g1; }
            *(float2*)(C + (size_t)ra * N + col)       = v0;
            *(float2*)(C + (size_t)(ra + 8) * N + col) = v1;
        }
    }
}

// ---------------------------------------------------------------------------
// Flash attention with tf32 mma. Block = 64 queries of one (b,h), 4 warps.
// NOTE: l0/l1 are fully reduced INSIDE the loop (ps shuffle); do NOT reduce
// again at the end (R1 bug: final re-reduction quadrupled l -> out/4).
// ---------------------------------------------------------------------------
__global__ __launch_bounds__(128) void attn_tf32(
    const float* __restrict__ qkv, const int* __restrict__ mask,
    float* __restrict__ out)
{
    extern __shared__ float sm[];
    float* Qhi = sm;                  // [64][68]
    float* Qlo = Qhi + 64 * 68;
    float* Ks  = Qlo + 64 * 68;       // [64][68]
    float* Vs  = Ks  + 64 * 68;       // [64][72]
    float* Ps  = Vs  + 64 * 72;       // [4][16][68]
    float* Mb  = Ps  + 4 * 16 * 68;   // [64]

    int t = threadIdx.x, lane = t & 31, w = t >> 5;
    int b = blockIdx.y >> 4, h = blockIdx.y & 15;
    int q0 = blockIdx.x * 64;
    const float* base = qkv + (size_t)b * SEQ * (3 * DIM) + h * (3 * HD);
    float* Pw = Ps + w * 16 * 68;

    #pragma unroll
    for (int i = 0; i < 8; i++) {
        int idx = t + i * 128;
        int r = idx >> 4, c = (idx & 15) * 4;
        float4 q4 = *(const float4*)(base + (size_t)(q0 + r) * (3 * DIM) + c);
        float hh;
        hh = tf32r(q4.x); Qhi[r*68+c+0] = hh; Qlo[r*68+c+0] = tf32r(q4.x - hh);
        hh = tf32r(q4.y); Qhi[r*68+c+1] = hh; Qlo[r*68+c+1] = tf32r(q4.y - hh);
        hh = tf32r(q4.z); Qhi[r*68+c+2] = hh; Qlo[r*68+c+2] = tf32r(q4.z - hh);
        hh = tf32r(q4.w); Qhi[r*68+c+3] = hh; Qlo[r*68+c+3] = tf32r(q4.w - hh);
    }

    float m0 = -INFINITY, m1 = -INFINITY, l0 = 0.f, l1 = 0.f;
    float o[8][4];
    #pragma unroll
    for (int nt = 0; nt < 8; nt++)
        #pragma unroll
        for (int i = 0; i < 4; i++) o[nt][i] = 0.f;

    for (int k0 = 0; k0 < SEQ; k0 += 64) {
        __syncthreads();
        #pragma unroll
        for (int i = 0; i < 8; i++) {
            int idx = t + i * 128;
            int r = idx >> 4, c = (idx & 15) * 4;
            const float* rp = base + (size_t)(k0 + r) * (3 * DIM);
            float4 k4 = *(const float4*)(rp + HD + c);
            Ks[r*68+c+0] = tf32r(k4.x); Ks[r*68+c+1] = tf32r(k4.y);
            Ks[r*68+c+2] = tf32r(k4.z); Ks[r*68+c+3] = tf32r(k4.w);
            float4 v4 = *(const float4*)(rp + 2 * HD + c);
            Vs[r*72+c+0] = tf32r(v4.x); Vs[r*72+c+1] = tf32r(v4.y);
            Vs[r*72+c+2] = tf32r(v4.z); Vs[r*72+c+3] = tf32r(v4.w);
        }
        if (t < 64) Mb[t] = mask[b * SEQ + k0 + t] ? 0.f : -1e30f;
        __syncthreads();

        float s[8][4];
        #pragma unroll
        for (int nt = 0; nt < 8; nt++)
            #pragma unroll
            for (int i = 0; i < 4; i++) s[nt][i] = 0.f;

        #pragma unroll
        for (int kt = 0; kt < 8; kt++) {
            int r = w * 16 + (lane >> 2);
            int c = kt * 8 + (lane & 3);
            uint32_t ah[4], al[4];
            ah[0] = __float_as_uint(Qhi[r*68 + c]);
            ah[1] = __float_as_uint(Qhi[(r+8)*68 + c]);
            ah[2] = __float_as_uint(Qhi[r*68 + c + 4]);
            ah[3] = __float_as_uint(Qhi[(r+8)*68 + c + 4]);
            al[0] = __float_as_uint(Qlo[r*68 + c]);
            al[1] = __float_as_uint(Qlo[(r+8)*68 + c]);
            al[2] = __float_as_uint(Qlo[r*68 + c + 4]);
            al[3] = __float_as_uint(Qlo[(r+8)*68 + c + 4]);
            #pragma unroll
            for (int nt = 0; nt < 8; nt++) {
                uint32_t bf[2];
                int n = nt * 8 + (lane >> 2);
                bf[0] = __float_as_uint(Ks[n*68 + c]);
                bf[1] = __float_as_uint(Ks[n*68 + c + 4]);
                mma8(s[nt], ah, bf);
                mma8(s[nt], al, bf);
            }
        }

        float rm0 = -INFINITY, rm1 = -INFINITY;
        #pragma unroll
        for (int nt = 0; nt < 8; nt++) {
            float2 bi = *(float2*)&Mb[nt * 8 + 2 * (lane & 3)];
            s[nt][0] = s[nt][0] * SCALE + bi.x;
            s[nt][1] = s[nt][1] * SCALE + bi.y;
            s[nt][2] = s[nt][2] * SCALE + bi.x;
            s[nt][3] = s[nt][3] * SCALE + bi.y;
            rm0 = fmaxf(rm0, fmaxf(s[nt][0], s[nt][1]));
            rm1 = fmaxf(rm1, fmaxf(s[nt][2], s[nt][3]));
        }
        rm0 = fmaxf(rm0, __shfl_xor_sync(0xffffffffu, rm0, 1));
        rm0 = fmaxf(rm0, __shfl_xor_sync(0xffffffffu, rm0, 2));
        rm1 = fmaxf(rm1, __shfl_xor_sync(0xffffffffu, rm1, 1));
        rm1 = fmaxf(rm1, __shfl_xor_sync(0xffffffffu, rm1, 2));

        float mn0 = fmaxf(m0, rm0), mn1 = fmaxf(m1, rm1);
        float sc0 = __expf(m0 - mn0), sc1 = __expf(m1 - mn1);
        m0 = mn0; m1 = mn1;

        float ps0 = 0.f, ps1 = 0.f;
        int r = (lane >> 2);
        #pragma unroll
        for (int nt = 0; nt < 8; nt++) {
            float p0 = (s[nt][0] < -1e29f) ? 0.f : __expf(s[nt][0] - mn0);
            float p1 = (s[nt][1] < -1e29f) ? 0.f : __expf(s[nt][1] - mn0);
            float p2 = (s[nt][2] < -1e29f) ? 0.f : __expf(s[nt][2] - mn1);
            float p3 = (s[nt][3] < -1e29f) ? 0.f : __expf(s[nt][3] - mn1);
            ps0 += p0 + p1; ps1 += p2 + p3;
            int cc = nt * 8 + 2 * (lane & 3);
            *(float2*)&Pw[r * 68 + cc]       = make_float2(tf32r(p0), tf32r(p1));
            *(float2*)&Pw[(r + 8) * 68 + cc] = make_float2(tf32r(p2), tf32r(p3));
        }
        ps0 += __shfl_xor_sync(0xffffffffu, ps0, 1);
        ps0 += __shfl_xor_sync(0xffffffffu, ps0, 2);
        ps1 += __shfl_xor_sync(0xffffffffu, ps1, 1);
        ps1 += __shfl_xor_sync(0xffffffffu, ps1, 2);
        l0 = l0 * sc0 + ps0;
        l1 = l1 * sc1 + ps1;

        #pragma unroll
        for (int nt = 0; nt < 8; nt++) {
            o[nt][0] *= sc0; o[nt][1] *= sc0;
            o[nt][2] *= sc1; o[nt][3] *= sc1;
        }
        __syncwarp();

        #pragma unroll
        for (int kt = 0; kt < 8; kt++) {
            uint32_t pa[4];
            int rr = (lane >> 2), cc = kt * 8 + (lane & 3);
            pa[0] = __float_as_uint(Pw[rr * 68 + cc]);
            pa[1] = __float_as_uint(Pw[(rr + 8) * 68 + cc]);
            pa[2] = __float_as_uint(Pw[rr * 68 + cc + 4]);
            pa[3] = __float_as_uint(Pw[(rr + 8) * 68 + cc + 4]);
            #pragma unroll
            for (int nt = 0; nt < 8; nt++) {
                uint32_t bf[2];
                int n = nt * 8 + (lane >> 2);
                bf[0] = __float_as_uint(Vs[(kt * 8 + (lane & 3)) * 72 + n]);
                bf[1] = __float_as_uint(Vs[(kt * 8 + (lane & 3) + 4) * 72 + n]);
                mma8(o[nt], pa, bf);
            }
        }
        __syncwarp();
    }

    // Finalize: l0/l1 are ALREADY the full row sums (reduced in-loop).
    float i0 = 1.f / l0, i1 = 1.f / l1;

    int ra = b * SEQ + q0 + w * 16 + (lane >> 2);
    #pragma unroll
    for (int nt = 0; nt < 8; nt++) {
        int col = h * HD + nt * 8 + 2 * (lane & 3);
        *(float2*)(out + (size_t)ra * DIM + col) =
            make_float2(o[nt][0] * i0, o[nt][1] * i0);
        *(float2*)(out + (size_t)(ra + 8) * DIM + col) =
            make_float2(o[nt][2] * i1, o[nt][3] * i1);
    }
}

// ---------------------------------------------------------------------------
extern "C" void kernel_launch(void* const* d_in, const int* in_sizes, int n_in,
                              void* d_out, int out_size)
{
    const float* x     = (const float*)d_in[0];
    const float* gamma = (const float*)d_in[1];
    const int*   mask  = (const int*)  d_in[2];
    const float* wqkv  = (const float*)d_in[3];
    const float* bqkv  = (const float*)d_in[4];
    const float* wo    = (const float*)d_in[5];
    const float* bo    = (const float*)d_in[6];
    float* out = (float*)d_out;

    float *qkv, *attn;
    cudaGetSymbolAddress((void**)&qkv,  g_qkv);
    cudaGetSymbolAddress((void**)&attn, g_attn);

    const int M = BSZ * SEQ;   // 4096

    // 1) QKV projection (3xTF32: near-fp32 exact)
    gemm_tf32<1, 0><<<dim3(3 * DIM / 128, M / 128), 256>>>(
        x, wqkv, bqkv, nullptr, qkv, M, 3 * DIM, DIM);

    // 2) Masked flash attention (tf32 tensor cores)
    size_t smem = (size_t)(3 * 64 * 68 + 64 * 72 + 4 * 16 * 68 + 64) * sizeof(float);
    cudaFuncSetAttribute(attn_tf32,
                         cudaFuncAttributeMaxDynamicSharedMemorySize, (int)smem);
    attn_tf32<<<dim3(SEQ / 64, BSZ * NH), 128, smem>>>(qkv, mask, attn);

    // 3) Output projection (A split) + bias + (gamma+1)
    gemm_tf32<0, 1><<<dim3(DIM / 128, M / 128), 256>>>(
        attn, wo, bo, gamma, out, M, DIM, DIM);
}

// round 5
// speedup vs baseline: 2.4209x; 1.2202x over previous
#include <cuda_runtime.h>
#include <cuda_bf16.h>
#include <math.h>
#include <stdint.h>

#define BSZ 2
#define SEQ 2048
#define DIM 1024
#define NH  16
#define HD  64
#define SCALE 0.125f

// Scratch (no cudaMalloc allowed)
__device__ float g_qkv[(size_t)BSZ * SEQ * 3 * DIM];   // [B,S,3D]
__device__ float g_attn[(size_t)BSZ * SEQ * DIM];      // [B,S,D]

// ---------------------------------------------------------------------------
// helpers
// ---------------------------------------------------------------------------
__device__ __forceinline__ uint32_t f2t(float x) {
    uint32_t u; asm("cvt.rna.tf32.f32 %0, %1;" : "=r"(u) : "f"(x)); return u;
}
__device__ __forceinline__ float tf32r(float x) { return __uint_as_float(f2t(x)); }

// tf32 m16n8k8 (attention)
__device__ __forceinline__ void mma8(float* c, const uint32_t* a, const uint32_t* b) {
    asm volatile(
        "mma.sync.aligned.m16n8k8.row.col.f32.tf32.tf32.f32 "
        "{%0,%1,%2,%3}, {%4,%5,%6,%7}, {%8,%9}, {%0,%1,%2,%3};\n"
        : "+f"(c[0]), "+f"(c[1]), "+f"(c[2]), "+f"(c[3])
        : "r"(a[0]), "r"(a[1]), "r"(a[2]), "r"(a[3]), "r"(b[0]), "r"(b[1]));
}

// bf16 m16n8k16 (projection GEMMs)
__device__ __forceinline__ void mma16(float* c, const uint32_t* a, uint32_t b0, uint32_t b1) {
    asm volatile(
        "mma.sync.aligned.m16n8k16.row.col.f32.bf16.bf16.f32 "
        "{%0,%1,%2,%3}, {%4,%5,%6,%7}, {%8,%9}, {%0,%1,%2,%3};\n"
        : "+f"(c[0]), "+f"(c[1]), "+f"(c[2]), "+f"(c[3])
        : "r"(a[0]), "r"(a[1]), "r"(a[2]), "r"(a[3]), "r"(b0), "r"(b1));
}

// bf16 hi/lo split: pack 2 floats -> (hi2, lo2) u32
__device__ __forceinline__ void split2(float a, float b, uint32_t& h, uint32_t& l) {
    __nv_bfloat16 ah = __float2bfloat16(a), bh = __float2bfloat16(b);
    __nv_bfloat16 al = __float2bfloat16(a - __bfloat162float(ah));
    __nv_bfloat16 bl = __float2bfloat16(b - __bfloat162float(bh));
    __nv_bfloat162 hv, lv;
    hv.x = ah; hv.y = bh; lv.x = al; lv.y = bl;
    h = *reinterpret_cast<uint32_t*>(&hv);
    l = *reinterpret_cast<uint32_t*>(&lv);
}

// ---------------------------------------------------------------------------
// bf16 GEMM (3-term split, near-fp32 exact): C = A@B + bias, opt *(gamma+1)
// Block 128x128, BK=32, 256 threads, 8 warps 4(m)x2(n), warp tile 32x64.
// Smem: A/B hi+lo as [row][k] bf16, row pad 40 (conflict-free frag reads).
// ---------------------------------------------------------------------------
template<int EPI>
__global__ __launch_bounds__(256) void gemm_bf16(
    const float* __restrict__ A, const float* __restrict__ B,
    const float* __restrict__ bias, const float* __restrict__ gamma,
    float* __restrict__ C, int M, int N, int K)
{
    __shared__ __nv_bfloat16 Ah[128][40], Al[128][40];
    __shared__ __nv_bfloat16 Bh[128][40], Bl[128][40];   // [n][k]

    int t = threadIdx.x, lane = t & 31, w = t >> 5;
    int wy = w >> 1, wx = w & 1;

    const float* Ab = A + (size_t)blockIdx.y * 128 * K;
    const float* Bb = B + (size_t)blockIdx.x * 128;

    float acc[2][8][4];
    #pragma unroll
    for (int mt = 0; mt < 2; mt++)
        #pragma unroll
        for (int nt = 0; nt < 8; nt++)
            #pragma unroll
            for (int i = 0; i < 4; i++) acc[mt][nt][i] = 0.f;

    for (int k0 = 0; k0 < K; k0 += 32) {
        // A tile 128x32: float4 loads, split -> Ah/Al
        #pragma unroll
        for (int i = 0; i < 4; i++) {
            int idx = t + i * 256;
            int r = idx >> 3, c4 = (idx & 7) * 4;
            float4 a4 = *(const float4*)(Ab + (size_t)r * K + k0 + c4);
            uint32_t h01, l01, h23, l23;
            split2(a4.x, a4.y, h01, l01);
            split2(a4.z, a4.w, h23, l23);
            *(uint2*)&Ah[r][c4] = make_uint2(h01, h23);
            *(uint2*)&Al[r][c4] = make_uint2(l01, l23);
        }
        // B tile 32x128 -> smem [n][k] (transpose in fill)
        #pragma unroll
        for (int i = 0; i < 4; i++) {
            int idx = t + i * 256;
            int n = idx & 127, kc = idx >> 7;   // kc 0..7, 4 k's each
            float v0 = Bb[(size_t)(k0 + kc * 4 + 0) * N + n];
            float v1 = Bb[(size_t)(k0 + kc * 4 + 1) * N + n];
            float v2 = Bb[(size_t)(k0 + kc * 4 + 2) * N + n];
            float v3 = Bb[(size_t)(k0 + kc * 4 + 3) * N + n];
            uint32_t h01, l01, h23, l23;
            split2(v0, v1, h01, l01);
            split2(v2, v3, h23, l23);
            *(uint2*)&Bh[n][kc * 4] = make_uint2(h01, h23);
            *(uint2*)&Bl[n][kc * 4] = make_uint2(l01, l23);
        }
        __syncthreads();

        #pragma unroll
        for (int ks = 0; ks < 2; ks++) {
            int kb = ks * 16 + (lane & 3) * 2;
            uint32_t ah[2][4], al[2][4];
            #pragma unroll
            for (int mt = 0; mt < 2; mt++) {
                int r = wy * 32 + mt * 16 + (lane >> 2);
                ah[mt][0] = *(uint32_t*)&Ah[r][kb];
                ah[mt][1] = *(uint32_t*)&Ah[r + 8][kb];
                ah[mt][2] = *(uint32_t*)&Ah[r][kb + 8];
                ah[mt][3] = *(uint32_t*)&Ah[r + 8][kb + 8];
                al[mt][0] = *(uint32_t*)&Al[r][kb];
                al[mt][1] = *(uint32_t*)&Al[r + 8][kb];
                al[mt][2] = *(uint32_t*)&Al[r][kb + 8];
                al[mt][3] = *(uint32_t*)&Al[r + 8][kb + 8];
            }
            #pragma unroll
            for (int nt = 0; nt < 8; nt++) {
                int n = wx * 64 + nt * 8 + (lane >> 2);
                uint32_t bh0 = *(uint32_t*)&Bh[n][kb];
                uint32_t bh1 = *(uint32_t*)&Bh[n][kb + 8];
                uint32_t bl0 = *(uint32_t*)&Bl[n][kb];
                uint32_t bl1 = *(uint32_t*)&Bl[n][kb + 8];
                #pragma unroll
                for (int mt = 0; mt < 2; mt++) {
                    mma16(acc[mt][nt], ah[mt], bh0, bh1);   // hi*hi
                    mma16(acc[mt][nt], al[mt], bh0, bh1);   // lo*hi
                    mma16(acc[mt][nt], ah[mt], bl0, bl1);   // hi*lo
                }
            }
        }
        __syncthreads();
    }

    // Epilogue (C fragment layout identical to tf32 k8)
    int r_base = blockIdx.y * 128 + wy * 32 + (lane >> 2);
    int c_base = blockIdx.x * 128 + wx * 64 + 2 * (lane & 3);
    #pragma unroll
    for (int nt = 0; nt < 8; nt++) {
        int col = c_base + nt * 8;
        float2 bi = *(const float2*)&bias[col];
        float g0 = 1.f, g1 = 1.f;
        if (EPI) {
            float2 gm = *(const float2*)&gamma[col];
            g0 = gm.x + 1.f; g1 = gm.y + 1.f;
        }
        #pragma unroll
        for (int mt = 0; mt < 2; mt++) {
            int ra = r_base + mt * 16;
            float2 v0, v1;
            v0.x = acc[mt][nt][0] + bi.x;
            v0.y = acc[mt][nt][1] + bi.y;
            v1.x = acc[mt][nt][2] + bi.x;
            v1.y = acc[mt][nt][3] + bi.y;
            if (EPI) { v0.x *= g0; v0.y *= g1; v1.x *= g0; v1.y *= g1; }
            *(float2*)(C + (size_t)ra * N + col)       = v0;
            *(float2*)(C + (size_t)(ra + 8) * N + col) = v1;
        }
    }
}

// ---------------------------------------------------------------------------
// Flash attention, tf32 warp mma (unchanged — passed at rel_err 3.5e-4).
// l0/l1 fully reduced in-loop; no final re-reduction.
// ---------------------------------------------------------------------------
__global__ __launch_bounds__(128) void attn_tf32(
    const float* __restrict__ qkv, const int* __restrict__ mask,
    float* __restrict__ out)
{
    extern __shared__ float sm[];
    float* Qhi = sm;                  // [64][68]
    float* Qlo = Qhi + 64 * 68;
    float* Ks  = Qlo + 64 * 68;       // [64][68]
    float* Vs  = Ks  + 64 * 68;       // [64][72]
    float* Ps  = Vs  + 64 * 72;       // [4][16][68]
    float* Mb  = Ps  + 4 * 16 * 68;   // [64]

    int t = threadIdx.x, lane = t & 31, w = t >> 5;
    int b = blockIdx.y >> 4, h = blockIdx.y & 15;
    int q0 = blockIdx.x * 64;
    const float* base = qkv + (size_t)b * SEQ * (3 * DIM) + h * (3 * HD);
    float* Pw = Ps + w * 16 * 68;

    #pragma unroll
    for (int i = 0; i < 8; i++) {
        int idx = t + i * 128;
        int r = idx >> 4, c = (idx & 15) * 4;
        float4 q4 = *(const float4*)(base + (size_t)(q0 + r) * (3 * DIM) + c);
        float hh;
        hh = tf32r(q4.x); Qhi[r*68+c+0] = hh; Qlo[r*68+c+0] = tf32r(q4.x - hh);
        hh = tf32r(q4.y); Qhi[r*68+c+1] = hh; Qlo[r*68+c+1] = tf32r(q4.y - hh);
        hh = tf32r(q4.z); Qhi[r*68+c+2] = hh; Qlo[r*68+c+2] = tf32r(q4.z - hh);
        hh = tf32r(q4.w); Qhi[r*68+c+3] = hh; Qlo[r*68+c+3] = tf32r(q4.w - hh);
    }

    float m0 = -INFINITY, m1 = -INFINITY, l0 = 0.f, l1 = 0.f;
    float o[8][4];
    #pragma unroll
    for (int nt = 0; nt < 8; nt++)
        #pragma unroll
        for (int i = 0; i < 4; i++) o[nt][i] = 0.f;

    for (int k0 = 0; k0 < SEQ; k0 += 64) {
        __syncthreads();
        #pragma unroll
        for (int i = 0; i < 8; i++) {
            int idx = t + i * 128;
            int r = idx >> 4, c = (idx & 15) * 4;
            const float* rp = base + (size_t)(k0 + r) * (3 * DIM);
            float4 k4 = *(const float4*)(rp + HD + c);
            Ks[r*68+c+0] = tf32r(k4.x); Ks[r*68+c+1] = tf32r(k4.y);
            Ks[r*68+c+2] = tf32r(k4.z); Ks[r*68+c+3] = tf32r(k4.w);
            float4 v4 = *(const float4*)(rp + 2 * HD + c);
            Vs[r*72+c+0] = tf32r(v4.x); Vs[r*72+c+1] = tf32r(v4.y);
            Vs[r*72+c+2] = tf32r(v4.z); Vs[r*72+c+3] = tf32r(v4.w);
        }
        if (t < 64) Mb[t] = mask[b * SEQ + k0 + t] ? 0.f : -1e30f;
        __syncthreads();

        float s[8][4];
        #pragma unroll
        for (int nt = 0; nt < 8; nt++)
            #pragma unroll
            for (int i = 0; i < 4; i++) s[nt][i] = 0.f;

        #pragma unroll
        for (int kt = 0; kt < 8; kt++) {
            int r = w * 16 + (lane >> 2);
            int c = kt * 8 + (lane & 3);
            uint32_t ah[4], al[4];
            ah[0] = __float_as_uint(Qhi[r*68 + c]);
            ah[1] = __float_as_uint(Qhi[(r+8)*68 + c]);
            ah[2] = __float_as_uint(Qhi[r*68 + c + 4]);
            ah[3] = __float_as_uint(Qhi[(r+8)*68 + c + 4]);
            al[0] = __float_as_uint(Qlo[r*68 + c]);
            al[1] = __float_as_uint(Qlo[(r+8)*68 + c]);
            al[2] = __float_as_uint(Qlo[r*68 + c + 4]);
            al[3] = __float_as_uint(Qlo[(r+8)*68 + c + 4]);
            #pragma unroll
            for (int nt = 0; nt < 8; nt++) {
                uint32_t bf[2];
                int n = nt * 8 + (lane >> 2);
                bf[0] = __float_as_uint(Ks[n*68 + c]);
                bf[1] = __float_as_uint(Ks[n*68 + c + 4]);
                mma8(s[nt], ah, bf);
                mma8(s[nt], al, bf);
            }
        }

        float rm0 = -INFINITY, rm1 = -INFINITY;
        #pragma unroll
        for (int nt = 0; nt < 8; nt++) {
            float2 bi = *(float2*)&Mb[nt * 8 + 2 * (lane & 3)];
            s[nt][0] = s[nt][0] * SCALE + bi.x;
            s[nt][1] = s[nt][1] * SCALE + bi.y;
            s[nt][2] = s[nt][2] * SCALE + bi.x;
            s[nt][3] = s[nt][3] * SCALE + bi.y;
            rm0 = fmaxf(rm0, fmaxf(s[nt][0], s[nt][1]));
            rm1 = fmaxf(rm1, fmaxf(s[nt][2], s[nt][3]));
        }
        rm0 = fmaxf(rm0, __shfl_xor_sync(0xffffffffu, rm0, 1));
        rm0 = fmaxf(rm0, __shfl_xor_sync(0xffffffffu, rm0, 2));
        rm1 = fmaxf(rm1, __shfl_xor_sync(0xffffffffu, rm1, 1));
        rm1 = fmaxf(rm1, __shfl_xor_sync(0xffffffffu, rm1, 2));

        float mn0 = fmaxf(m0, rm0), mn1 = fmaxf(m1, rm1);
        float sc0 = __expf(m0 - mn0), sc1 = __expf(m1 - mn1);
        m0 = mn0; m1 = mn1;

        float ps0 = 0.f, ps1 = 0.f;
        int r = (lane >> 2);
        #pragma unroll
        for (int nt = 0; nt < 8; nt++) {
            float p0 = (s[nt][0] < -1e29f) ? 0.f : __expf(s[nt][0] - mn0);
            float p1 = (s[nt][1] < -1e29f) ? 0.f : __expf(s[nt][1] - mn0);
            float p2 = (s[nt][2] < -1e29f) ? 0.f : __expf(s[nt][2] - mn1);
            float p3 = (s[nt][3] < -1e29f) ? 0.f : __expf(s[nt][3] - mn1);
            ps0 += p0 + p1; ps1 += p2 + p3;
            int cc = nt * 8 + 2 * (lane & 3);
            *(float2*)&Pw[r * 68 + cc]       = make_float2(tf32r(p0), tf32r(p1));
            *(float2*)&Pw[(r + 8) * 68 + cc] = make_float2(tf32r(p2), tf32r(p3));
        }
        ps0 += __shfl_xor_sync(0xffffffffu, ps0, 1);
        ps0 += __shfl_xor_sync(0xffffffffu, ps0, 2);
        ps1 += __shfl_xor_sync(0xffffffffu, ps1, 1);
        ps1 += __shfl_xor_sync(0xffffffffu, ps1, 2);
        l0 = l0 * sc0 + ps0;
        l1 = l1 * sc1 + ps1;

        #pragma unroll
        for (int nt = 0; nt < 8; nt++) {
            o[nt][0] *= sc0; o[nt][1] *= sc0;
            o[nt][2] *= sc1; o[nt][3] *= sc1;
        }
        __syncwarp();

        #pragma unroll
        for (int kt = 0; kt < 8; kt++) {
            uint32_t pa[4];
            int rr = (lane >> 2), cc = kt * 8 + (lane & 3);
            pa[0] = __float_as_uint(Pw[rr * 68 + cc]);
            pa[1] = __float_as_uint(Pw[(rr + 8) * 68 + cc]);
            pa[2] = __float_as_uint(Pw[rr * 68 + cc + 4]);
            pa[3] = __float_as_uint(Pw[(rr + 8) * 68 + cc + 4]);
            #pragma unroll
            for (int nt = 0; nt < 8; nt++) {
                uint32_t bf[2];
                int n = nt * 8 + (lane >> 2);
                bf[0] = __float_as_uint(Vs[(kt * 8 + (lane & 3)) * 72 + n]);
                bf[1] = __float_as_uint(Vs[(kt * 8 + (lane & 3) + 4) * 72 + n]);
                mma8(o[nt], pa, bf);
            }
        }
        __syncwarp();
    }

    float i0 = 1.f / l0, i1 = 1.f / l1;
    int ra = b * SEQ + q0 + w * 16 + (lane >> 2);
    #pragma unroll
    for (int nt = 0; nt < 8; nt++) {
        int col = h * HD + nt * 8 + 2 * (lane & 3);
        *(float2*)(out + (size_t)ra * DIM + col) =
            make_float2(o[nt][0] * i0, o[nt][1] * i0);
        *(float2*)(out + (size_t)(ra + 8) * DIM + col) =
            make_float2(o[nt][2] * i1, o[nt][3] * i1);
    }
}

// ---------------------------------------------------------------------------
extern "C" void kernel_launch(void* const* d_in, const int* in_sizes, int n_in,
                              void* d_out, int out_size)
{
    (void)in_sizes; (void)n_in; (void)out_size;
    const float* x     = (const float*)d_in[0];
    const float* gamma = (const float*)d_in[1];
    const int*   mask  = (const int*)  d_in[2];
    const float* wqkv  = (const float*)d_in[3];
    const float* bqkv  = (const float*)d_in[4];
    const float* wo    = (const float*)d_in[5];
    const float* bo    = (const float*)d_in[6];
    float* out = (float*)d_out;

    float *qkv, *attn;
    cudaGetSymbolAddress((void**)&qkv,  g_qkv);
    cudaGetSymbolAddress((void**)&attn, g_attn);

    const int M = BSZ * SEQ;   // 4096

    // 1) QKV projection (bf16 m16n8k16, 3-term split)
    gemm_bf16<0><<<dim3(3 * DIM / 128, M / 128), 256>>>(
        x, wqkv, bqkv, nullptr, qkv, M, 3 * DIM, DIM);

    // 2) Masked flash attention (tf32 warp mma)
    size_t smem = (size_t)(3 * 64 * 68 + 64 * 72 + 4 * 16 * 68 + 64) * sizeof(float);
    cudaFuncSetAttribute(attn_tf32,
                         cudaFuncAttributeMaxDynamicSharedMemorySize, (int)smem);
    attn_tf32<<<dim3(SEQ / 64, BSZ * NH), 128, smem>>>(qkv, mask, attn);

    // 3) Output projection (bf16) + bias + (gamma+1)
    gemm_bf16<1><<<dim3(DIM / 128, M / 128), 256>>>(
        attn, wo, bo, gamma, out, M, DIM, DIM);
}

// round 6
// speedup vs baseline: 3.1916x; 1.3184x over previous
#include <cuda_runtime.h>
#include <cuda_bf16.h>
#include <math.h>
#include <stdint.h>

#define BSZ 2
#define SEQ 2048
#define DIM 1024
#define NH  16
#define HD  64
#define SCALE 0.125f

// Scratch (no cudaMalloc allowed)
__device__ float g_qkv[(size_t)BSZ * SEQ * 3 * DIM];   // [B,S,3D]
__device__ float g_attn[(size_t)BSZ * SEQ * DIM];      // [B,S,D]

// ---------------------------------------------------------------------------
// helpers
// ---------------------------------------------------------------------------
__device__ __forceinline__ uint32_t f2t(float x) {
    uint32_t u; asm("cvt.rna.tf32.f32 %0, %1;" : "=r"(u) : "f"(x)); return u;
}
__device__ __forceinline__ float tf32r(float x) { return __uint_as_float(f2t(x)); }

// tf32 m16n8k8 (attention)
__device__ __forceinline__ void mma8(float* c, const uint32_t* a, const uint32_t* b) {
    asm volatile(
        "mma.sync.aligned.m16n8k8.row.col.f32.tf32.tf32.f32 "
        "{%0,%1,%2,%3}, {%4,%5,%6,%7}, {%8,%9}, {%0,%1,%2,%3};\n"
        : "+f"(c[0]), "+f"(c[1]), "+f"(c[2]), "+f"(c[3])
        : "r"(a[0]), "r"(a[1]), "r"(a[2]), "r"(a[3]), "r"(b[0]), "r"(b[1]));
}

// bf16 m16n8k16 (projection GEMMs)
__device__ __forceinline__ void mma16(float* c, const uint32_t* a, uint32_t b0, uint32_t b1) {
    asm volatile(
        "mma.sync.aligned.m16n8k16.row.col.f32.bf16.bf16.f32 "
        "{%0,%1,%2,%3}, {%4,%5,%6,%7}, {%8,%9}, {%0,%1,%2,%3};\n"
        : "+f"(c[0]), "+f"(c[1]), "+f"(c[2]), "+f"(c[3])
        : "r"(a[0]), "r"(a[1]), "r"(a[2]), "r"(a[3]), "r"(b0), "r"(b1));
}

// bf16 hi/lo split: pack 2 floats -> (hi2, lo2) u32
__device__ __forceinline__ void split2(float a, float b, uint32_t& h, uint32_t& l) {
    __nv_bfloat16 ah = __float2bfloat16(a), bh = __float2bfloat16(b);
    __nv_bfloat16 al = __float2bfloat16(a - __bfloat162float(ah));
    __nv_bfloat16 bl = __float2bfloat16(b - __bfloat162float(bh));
    __nv_bfloat162 hv, lv;
    hv.x = ah; hv.y = bh; lv.x = al; lv.y = bl;
    h = *reinterpret_cast<uint32_t*>(&hv);
    l = *reinterpret_cast<uint32_t*>(&lv);
}

// ---------------------------------------------------------------------------
// bf16 GEMM (3-term split, near-fp32 exact) with register-prefetch pipeline:
// gmem loads for tile it+1 are issued before the mma phase of tile it, so
// DRAM/L2 latency retires under the tensor work (1 CTA/SM, no co-tenant).
// Block 128x128, BK=32, 256 threads, 8 warps 4(m)x2(n).
// ---------------------------------------------------------------------------
template<int EPI>
__global__ __launch_bounds__(256) void gemm_bf16(
    const float* __restrict__ A, const float* __restrict__ B,
    const float* __restrict__ bias, const float* __restrict__ gamma,
    float* __restrict__ C, int M, int N, int K)
{
    __shared__ __nv_bfloat16 Ah[128][40], Al[128][40];
    __shared__ __nv_bfloat16 Bh[128][40], Bl[128][40];   // [n][k]

    int t = threadIdx.x, lane = t & 31, w = t >> 5;
    int wy = w >> 1, wx = w & 1;

    const float* Ab = A + (size_t)blockIdx.y * 128 * K;
    const float* Bb = B + (size_t)blockIdx.x * 128;

    // per-thread fill coordinates
    int ar = t >> 1, ac4 = (t & 1) * 16;            // A: 2 float4 groups? no:
    // A tile 128x32 floats: idx = t + i*256; r = idx>>3, c4 = (idx&7)*4 (4 groups)
    // B tile 32x128: idx = t + i*256; n = idx&127, kc = idx>>7 (4 groups of 4 k)
    (void)ar; (void)ac4;

    float acc[2][8][4];
    #pragma unroll
    for (int mt = 0; mt < 2; mt++)
        #pragma unroll
        for (int nt = 0; nt < 8; nt++)
            #pragma unroll
            for (int i = 0; i < 4; i++) acc[mt][nt][i] = 0.f;

    float4 aR[4];
    float  bR[4][4];

    // prefetch tile 0
    {
        #pragma unroll
        for (int i = 0; i < 4; i++) {
            int idx = t + i * 256;
            int r = idx >> 3, c4 = (idx & 7) * 4;
            aR[i] = *(const float4*)(Ab + (size_t)r * K + c4);
        }
        #pragma unroll
        for (int i = 0; i < 4; i++) {
            int idx = t + i * 256;
            int n = idx & 127, kc = idx >> 7;
            #pragma unroll
            for (int j = 0; j < 4; j++)
                bR[i][j] = Bb[(size_t)(kc * 4 + j) * N + n];
        }
    }

    const int ITERS = K / 32;
    for (int it = 0; it < ITERS; it++) {
        // store prefetched regs -> smem (split hi/lo)
        #pragma unroll
        for (int i = 0; i < 4; i++) {
            int idx = t + i * 256;
            int r = idx >> 3, c4 = (idx & 7) * 4;
            uint32_t h01, l01, h23, l23;
            split2(aR[i].x, aR[i].y, h01, l01);
            split2(aR[i].z, aR[i].w, h23, l23);
            *(uint2*)&Ah[r][c4] = make_uint2(h01, h23);
            *(uint2*)&Al[r][c4] = make_uint2(l01, l23);
        }
        #pragma unroll
        for (int i = 0; i < 4; i++) {
            int idx = t + i * 256;
            int n = idx & 127, kc = idx >> 7;
            uint32_t h01, l01, h23, l23;
            split2(bR[i][0], bR[i][1], h01, l01);
            split2(bR[i][2], bR[i][3], h23, l23);
            *(uint2*)&Bh[n][kc * 4] = make_uint2(h01, h23);
            *(uint2*)&Bl[n][kc * 4] = make_uint2(l01, l23);
        }
        __syncthreads();

        // issue gmem loads for next tile (retire during mma below)
        if (it + 1 < ITERS) {
            int k0n = (it + 1) * 32;
            #pragma unroll
            for (int i = 0; i < 4; i++) {
                int idx = t + i * 256;
                int r = idx >> 3, c4 = (idx & 7) * 4;
                aR[i] = *(const float4*)(Ab + (size_t)r * K + k0n + c4);
            }
            #pragma unroll
            for (int i = 0; i < 4; i++) {
                int idx = t + i * 256;
                int n = idx & 127, kc = idx >> 7;
                #pragma unroll
                for (int j = 0; j < 4; j++)
                    bR[i][j] = Bb[(size_t)(k0n + kc * 4 + j) * N + n];
            }
        }

        // mma phase
        #pragma unroll
        for (int ks = 0; ks < 2; ks++) {
            int kb = ks * 16 + (lane & 3) * 2;
            uint32_t ah[2][4], al[2][4];
            #pragma unroll
            for (int mt = 0; mt < 2; mt++) {
                int r = wy * 32 + mt * 16 + (lane >> 2);
                ah[mt][0] = *(uint32_t*)&Ah[r][kb];
                ah[mt][1] = *(uint32_t*)&Ah[r + 8][kb];
                ah[mt][2] = *(uint32_t*)&Ah[r][kb + 8];
                ah[mt][3] = *(uint32_t*)&Ah[r + 8][kb + 8];
                al[mt][0] = *(uint32_t*)&Al[r][kb];
                al[mt][1] = *(uint32_t*)&Al[r + 8][kb];
                al[mt][2] = *(uint32_t*)&Al[r][kb + 8];
                al[mt][3] = *(uint32_t*)&Al[r + 8][kb + 8];
            }
            #pragma unroll
            for (int nt = 0; nt < 8; nt++) {
                int n = wx * 64 + nt * 8 + (lane >> 2);
                uint32_t bh0 = *(uint32_t*)&Bh[n][kb];
                uint32_t bh1 = *(uint32_t*)&Bh[n][kb + 8];
                uint32_t bl0 = *(uint32_t*)&Bl[n][kb];
                uint32_t bl1 = *(uint32_t*)&Bl[n][kb + 8];
                #pragma unroll
                for (int mt = 0; mt < 2; mt++) {
                    mma16(acc[mt][nt], ah[mt], bh0, bh1);   // hi*hi
                    mma16(acc[mt][nt], al[mt], bh0, bh1);   // lo*hi
                    mma16(acc[mt][nt], ah[mt], bl0, bl1);   // hi*lo
                }
            }
        }
        __syncthreads();
    }

    // Epilogue
    int r_base = blockIdx.y * 128 + wy * 32 + (lane >> 2);
    int c_base = blockIdx.x * 128 + wx * 64 + 2 * (lane & 3);
    #pragma unroll
    for (int nt = 0; nt < 8; nt++) {
        int col = c_base + nt * 8;
        float2 bi = *(const float2*)&bias[col];
        float g0 = 1.f, g1 = 1.f;
        if (EPI) {
            float2 gm = *(const float2*)&gamma[col];
            g0 = gm.x + 1.f; g1 = gm.y + 1.f;
        }
        #pragma unroll
        for (int mt = 0; mt < 2; mt++) {
            int ra = r_base + mt * 16;
            float2 v0, v1;
            v0.x = acc[mt][nt][0] + bi.x;
            v0.y = acc[mt][nt][1] + bi.y;
            v1.x = acc[mt][nt][2] + bi.x;
            v1.y = acc[mt][nt][3] + bi.y;
            if (EPI) { v0.x *= g0; v0.y *= g1; v1.x *= g0; v1.y *= g1; }
            *(float2*)(C + (size_t)ra * N + col)       = v0;
            *(float2*)(C + (size_t)(ra + 8) * N + col) = v1;
        }
    }
}

// ---------------------------------------------------------------------------
// Flash attention, tf32 warp mma. QK^T now SINGLE tf32 x tf32 (Q split
// dropped: adds ~2e-4 to rel_err, halves QK tensor work). PV unchanged.
// l0/l1 fully reduced in-loop; no final re-reduction.
// ---------------------------------------------------------------------------
__global__ __launch_bounds__(128) void attn_tf32(
    const float* __restrict__ qkv, const int* __restrict__ mask,
    float* __restrict__ out)
{
    extern __shared__ float sm[];
    float* Qs = sm;                   // [64][68]
    float* Ks = Qs + 64 * 68;         // [64][68]
    float* Vs = Ks + 64 * 68;         // [64][72]
    float* Ps = Vs + 64 * 72;         // [4][16][68]
    float* Mb = Ps + 4 * 16 * 68;     // [64]

    int t = threadIdx.x, lane = t & 31, w = t >> 5;
    int b = blockIdx.y >> 4, h = blockIdx.y & 15;
    int q0 = blockIdx.x * 64;
    const float* base = qkv + (size_t)b * SEQ * (3 * DIM) + h * (3 * HD);
    float* Pw = Ps + w * 16 * 68;

    #pragma unroll
    for (int i = 0; i < 8; i++) {
        int idx = t + i * 128;
        int r = idx >> 4, c = (idx & 15) * 4;
        float4 q4 = *(const float4*)(base + (size_t)(q0 + r) * (3 * DIM) + c);
        Qs[r*68+c+0] = tf32r(q4.x); Qs[r*68+c+1] = tf32r(q4.y);
        Qs[r*68+c+2] = tf32r(q4.z); Qs[r*68+c+3] = tf32r(q4.w);
    }

    float m0 = -INFINITY, m1 = -INFINITY, l0 = 0.f, l1 = 0.f;
    float o[8][4];
    #pragma unroll
    for (int nt = 0; nt < 8; nt++)
        #pragma unroll
        for (int i = 0; i < 4; i++) o[nt][i] = 0.f;

    for (int k0 = 0; k0 < SEQ; k0 += 64) {
        __syncthreads();
        #pragma unroll
        for (int i = 0; i < 8; i++) {
            int idx = t + i * 128;
            int r = idx >> 4, c = (idx & 15) * 4;
            const float* rp = base + (size_t)(k0 + r) * (3 * DIM);
            float4 k4 = *(const float4*)(rp + HD + c);
            Ks[r*68+c+0] = tf32r(k4.x); Ks[r*68+c+1] = tf32r(k4.y);
            Ks[r*68+c+2] = tf32r(k4.z); Ks[r*68+c+3] = tf32r(k4.w);
            float4 v4 = *(const float4*)(rp + 2 * HD + c);
            Vs[r*72+c+0] = tf32r(v4.x); Vs[r*72+c+1] = tf32r(v4.y);
            Vs[r*72+c+2] = tf32r(v4.z); Vs[r*72+c+3] = tf32r(v4.w);
        }
        if (t < 64) Mb[t] = mask[b * SEQ + k0 + t] ? 0.f : -1e30f;
        __syncthreads();

        float s[8][4];
        #pragma unroll
        for (int nt = 0; nt < 8; nt++)
            #pragma unroll
            for (int i = 0; i < 4; i++) s[nt][i] = 0.f;

        #pragma unroll
        for (int kt = 0; kt < 8; kt++) {
            int r = w * 16 + (lane >> 2);
            int c = kt * 8 + (lane & 3);
            uint32_t ah[4];
            ah[0] = __float_as_uint(Qs[r*68 + c]);
            ah[1] = __float_as_uint(Qs[(r+8)*68 + c]);
            ah[2] = __float_as_uint(Qs[r*68 + c + 4]);
            ah[3] = __float_as_uint(Qs[(r+8)*68 + c + 4]);
            #pragma unroll
            for (int nt = 0; nt < 8; nt++) {
                uint32_t bf[2];
                int n = nt * 8 + (lane >> 2);
                bf[0] = __float_as_uint(Ks[n*68 + c]);
                bf[1] = __float_as_uint(Ks[n*68 + c + 4]);
                mma8(s[nt], ah, bf);
            }
        }

        float rm0 = -INFINITY, rm1 = -INFINITY;
        #pragma unroll
        for (int nt = 0; nt < 8; nt++) {
            float2 bi = *(float2*)&Mb[nt * 8 + 2 * (lane & 3)];
            s[nt][0] = s[nt][0] * SCALE + bi.x;
            s[nt][1] = s[nt][1] * SCALE + bi.y;
            s[nt][2] = s[nt][2] * SCALE + bi.x;
            s[nt][3] = s[nt][3] * SCALE + bi.y;
            rm0 = fmaxf(rm0, fmaxf(s[nt][0], s[nt][1]));
            rm1 = fmaxf(rm1, fmaxf(s[nt][2], s[nt][3]));
        }
        rm0 = fmaxf(rm0, __shfl_xor_sync(0xffffffffu, rm0, 1));
        rm0 = fmaxf(rm0, __shfl_xor_sync(0xffffffffu, rm0, 2));
        rm1 = fmaxf(rm1, __shfl_xor_sync(0xffffffffu, rm1, 1));
        rm1 = fmaxf(rm1, __shfl_xor_sync(0xffffffffu, rm1, 2));

        float mn0 = fmaxf(m0, rm0), mn1 = fmaxf(m1, rm1);
        float sc0 = __expf(m0 - mn0), sc1 = __expf(m1 - mn1);
        m0 = mn0; m1 = mn1;

        float ps0 = 0.f, ps1 = 0.f;
        int r = (lane >> 2);
        #pragma unroll
        for (int nt = 0; nt < 8; nt++) {
            float p0 = (s[nt][0] < -1e29f) ? 0.f : __expf(s[nt][0] - mn0);
            float p1 = (s[nt][1] < -1e29f) ? 0.f : __expf(s[nt][1] - mn0);
            float p2 = (s[nt][2] < -1e29f) ? 0.f : __expf(s[nt][2] - mn1);
            float p3 = (s[nt][3] < -1e29f) ? 0.f : __expf(s[nt][3] - mn1);
            ps0 += p0 + p1; ps1 += p2 + p3;
            int cc = nt * 8 + 2 * (lane & 3);
            *(float2*)&Pw[r * 68 + cc]       = make_float2(tf32r(p0), tf32r(p1));
            *(float2*)&Pw[(r + 8) * 68 + cc] = make_float2(tf32r(p2), tf32r(p3));
        }
        ps0 += __shfl_xor_sync(0xffffffffu, ps0, 1);
        ps0 += __shfl_xor_sync(0xffffffffu, ps0, 2);
        ps1 += __shfl_xor_sync(0xffffffffu, ps1, 1);
        ps1 += __shfl_xor_sync(0xffffffffu, ps1, 2);
        l0 = l0 * sc0 + ps0;
        l1 = l1 * sc1 + ps1;

        #pragma unroll
        for (int nt = 0; nt < 8; nt++) {
            o[nt][0] *= sc0; o[nt][1] *= sc0;
            o[nt][2] *= sc1; o[nt][3] *= sc1;
        }
        __syncwarp();

        #pragma unroll
        for (int kt = 0; kt < 8; kt++) {
            uint32_t pa[4];
            int rr = (lane >> 2), cc = kt * 8 + (lane & 3);
            pa[0] = __float_as_uint(Pw[rr * 68 + cc]);
            pa[1] = __float_as_uint(Pw[(rr + 8) * 68 + cc]);
            pa[2] = __float_as_uint(Pw[rr * 68 + cc + 4]);
            pa[3] = __float_as_uint(Pw[(rr + 8) * 68 + cc + 4]);
            #pragma unroll
            for (int nt = 0; nt < 8; nt++) {
                uint32_t bf[2];
                int n = nt * 8 + (lane >> 2);
                bf[0] = __float_as_uint(Vs[(kt * 8 + (lane & 3)) * 72 + n]);
                bf[1] = __float_as_uint(Vs[(kt * 8 + (lane & 3) + 4) * 72 + n]);
                mma8(o[nt], pa, bf);
            }
        }
        __syncwarp();
    }

    float i0 = 1.f / l0, i1 = 1.f / l1;
    int ra = b * SEQ + q0 + w * 16 + (lane >> 2);
    #pragma unroll
    for (int nt = 0; nt < 8; nt++) {
        int col = h * HD + nt * 8 + 2 * (lane & 3);
        *(float2*)(out + (size_t)ra * DIM + col) =
            make_float2(o[nt][0] * i0, o[nt][1] * i0);
        *(float2*)(out + (size_t)(ra + 8) * DIM + col) =
            make_float2(o[nt][2] * i1, o[nt][3] * i1);
    }
}

// ---------------------------------------------------------------------------
extern "C" void kernel_launch(void* const* d_in, const int* in_sizes, int n_in,
                              void* d_out, int out_size)
{
    (void)in_sizes; (void)n_in; (void)out_size;
    const float* x     = (const float*)d_in[0];
    const float* gamma = (const float*)d_in[1];
    const int*   mask  = (const int*)  d_in[2];
    const float* wqkv  = (const float*)d_in[3];
    const float* bqkv  = (const float*)d_in[4];
    const float* wo    = (const float*)d_in[5];
    const float* bo    = (const float*)d_in[6];
    float* out = (float*)d_out;

    float *qkv, *attn;
    cudaGetSymbolAddress((void**)&qkv,  g_qkv);
    cudaGetSymbolAddress((void**)&attn, g_attn);

    const int M = BSZ * SEQ;   // 4096

    // 1) QKV projection (bf16 m16n8k16, 3-term split, reg prefetch)
    gemm_bf16<0><<<dim3(3 * DIM / 128, M / 128), 256>>>(
        x, wqkv, bqkv, nullptr, qkv, M, 3 * DIM, DIM);

    // 2) Masked flash attention (tf32 warp mma, single-term QK)
    size_t smem = (size_t)(2 * 64 * 68 + 64 * 72 + 4 * 16 * 68 + 64) * sizeof(float);
    cudaFuncSetAttribute(attn_tf32,
                         cudaFuncAttributeMaxDynamicSharedMemorySize, (int)smem);
    attn_tf32<<<dim3(SEQ / 64, BSZ * NH), 128, smem>>>(qkv, mask, attn);

    // 3) Output projection (bf16, reg prefetch) + bias + (gamma+1)
    gemm_bf16<1><<<dim3(DIM / 128, M / 128), 256>>>(
        attn, wo, bo, gamma, out, M, DIM, DIM);
}